// round 1
// baseline (speedup 1.0000x reference)
#include <cuda_runtime.h>
#include <math.h>

#define NN 10000
#define EE 160000
#define FF 4
#define TT 12
#define CC 512
#define HIDN 256
#define OUTD 12

// ---------------- scratch (device globals; no allocation allowed) -------------
__device__ float g_deg[NN];
__device__ float g_dinv[NN];
__device__ float g_agg[NN * FF * TT];   // [n][t][f]  (t*4+f)
__device__ float g_Weff[3 * FF * CC];   // gate-major: [gate][f][c]
__device__ float g_beff[3 * CC];
__device__ float g_probs[TT];
__device__ float g_H[NN * CC];
__device__ float g_ACC[NN * CC];
__device__ float g_Z[NN * CC];
__device__ float g_HR[NN * CC];
__device__ float g_h1[NN * HIDN];

// ---------------- graph-normalization prep ----------------
__global__ void init_deg_kernel() {
    int i = blockIdx.x * blockDim.x + threadIdx.x;
    if (i < NN) g_deg[i] = 1.0f;   // self loop weight
}

__global__ void deg_edges_kernel(const int* __restrict__ ei, const float* __restrict__ ea) {
    int e = blockIdx.x * blockDim.x + threadIdx.x;
    if (e < EE) atomicAdd(&g_deg[ei[EE + e]], ea[e]);
}

__global__ void dinv_kernel() {
    int i = blockIdx.x * blockDim.x + threadIdx.x;
    if (i < NN) g_dinv[i] = rsqrtf(fmaxf(g_deg[i], 1e-12f));
}

// self-loop term: agg[n][t][f] = dinv[n]^2 * x[n][f][t]
__global__ void agg_init_kernel(const float* __restrict__ x) {
    int idx = blockIdx.x * blockDim.x + threadIdx.x;
    if (idx >= NN * 48) return;
    int n = idx / 48;
    int k = idx % 48;       // k = t*4 + f
    int t = k >> 2;
    int f = k & 3;
    float di = g_dinv[n];
    g_agg[idx] = di * di * x[n * 48 + f * 12 + t];
}

__global__ void agg_edges_kernel(const float* __restrict__ x,
                                 const int* __restrict__ ei,
                                 const float* __restrict__ ea) {
    long long idx = (long long)blockIdx.x * blockDim.x + threadIdx.x;
    if (idx >= (long long)EE * 48) return;
    int e = (int)(idx / 48);
    int k = (int)(idx % 48);
    int t = k >> 2;
    int f = k & 3;
    int s = ei[e];
    int d = ei[EE + e];
    float nrm = g_dinv[s] * ea[e] * g_dinv[d];
    atomicAdd(&g_agg[(long long)d * 48 + k], nrm * x[s * 48 + f * 12 + t]);
}

// ---------------- weight folding: Weff = Wg @ Wl_top, beff = bg @ Wl_top + bl --
__global__ void weff_kernel(const float* __restrict__ Wg, const float* __restrict__ bg,
                            const float* __restrict__ Wl, const float* __restrict__ bl,
                            int gate) {
    int idx = blockIdx.x * blockDim.x + threadIdx.x;
    if (idx >= 5 * CC) return;
    int row = idx / CC;     // 0..3 = Weff rows, 4 = bias
    int c = idx % CC;
    if (row < 4) {
        float s = 0.f;
        for (int k = 0; k < CC; ++k) s += Wg[row * CC + k] * Wl[k * CC + c];
        g_Weff[gate * 4 * CC + row * CC + c] = s;
    } else {
        float s = bl[c];
        for (int k = 0; k < CC; ++k) s += bg[k] * Wl[k * CC + c];
        g_beff[gate * CC + c] = s;
    }
}

__global__ void softmax_att_kernel(const float* __restrict__ att) {
    if (threadIdx.x == 0 && blockIdx.x == 0) {
        float m = -1e30f;
        for (int t = 0; t < TT; ++t) m = fmaxf(m, att[t]);
        float s = 0.f;
        float e[TT];
        for (int t = 0; t < TT; ++t) { e[t] = expf(att[t] - m); s += e[t]; }
        float inv = 1.0f / s;
        for (int t = 0; t < TT; ++t) g_probs[t] = e[t] * inv;
    }
}

__global__ void zero_HA_kernel() {
    int i = blockIdx.x * blockDim.x + threadIdx.x;
    if (i < NN * CC) { g_H[i] = 0.f; g_ACC[i] = 0.f; }
}

// ---------------- GEMM tiles ----------------
#define BM 64
#define BN 64
#define BK 32

// z & r fused: z = sigmoid(Xa@WeffZ + H@WzL_bot + beffZ); r likewise; HR = H*r
__global__ __launch_bounds__(256) void gemm_zr_kernel(const float* __restrict__ Wzl,
                                                      const float* __restrict__ Wrl,
                                                      int t) {
    __shared__ float As[BK][BM + 1];
    __shared__ float Bz[BK][BN];
    __shared__ float Br[BK][BN];
    int tid = threadIdx.x;
    int tx = tid & 15, ty = tid >> 4;
    int m0 = blockIdx.x * BM;
    int n0 = blockIdx.y * BN;
    const float* BzP = Wzl + CC * CC;   // bottom half rows
    const float* BrP = Wrl + CC * CC;

    float az[4][4], ar[4][4];
#pragma unroll
    for (int i = 0; i < 4; ++i)
#pragma unroll
        for (int j = 0; j < 4; ++j) { az[i][j] = 0.f; ar[i][j] = 0.f; }

    int lr = tid >> 3;            // 0..31
    int lc = (tid & 7) << 2;      // 0,4,..28
    int brw = tid >> 4;           // 0..15
    int bcc = (tid & 15) << 2;    // 0..60

    for (int k0 = 0; k0 < CC; k0 += BK) {
#pragma unroll
        for (int it = 0; it < 2; ++it) {
            int m = m0 + lr + it * 32;
            float4 v = make_float4(0.f, 0.f, 0.f, 0.f);
            if (m < NN) v = *(const float4*)(g_H + (size_t)m * CC + k0 + lc);
            As[lc + 0][lr + it * 32] = v.x;
            As[lc + 1][lr + it * 32] = v.y;
            As[lc + 2][lr + it * 32] = v.z;
            As[lc + 3][lr + it * 32] = v.w;
        }
#pragma unroll
        for (int it = 0; it < 2; ++it) {
            int kk = brw + it * 16;
            *(float4*)&Bz[kk][bcc] = *(const float4*)(BzP + (size_t)(k0 + kk) * CC + n0 + bcc);
            *(float4*)&Br[kk][bcc] = *(const float4*)(BrP + (size_t)(k0 + kk) * CC + n0 + bcc);
        }
        __syncthreads();
#pragma unroll
        for (int kk = 0; kk < BK; ++kk) {
            float a[4];
#pragma unroll
            for (int i = 0; i < 4; ++i) a[i] = As[kk][ty * 4 + i];
            float4 bz4 = *(float4*)&Bz[kk][tx * 4];
            float4 br4 = *(float4*)&Br[kk][tx * 4];
#pragma unroll
            for (int i = 0; i < 4; ++i) {
                az[i][0] += a[i] * bz4.x; az[i][1] += a[i] * bz4.y;
                az[i][2] += a[i] * bz4.z; az[i][3] += a[i] * bz4.w;
                ar[i][0] += a[i] * br4.x; ar[i][1] += a[i] * br4.y;
                ar[i][2] += a[i] * br4.z; ar[i][3] += a[i] * br4.w;
            }
        }
        __syncthreads();
    }

    const float* WeZ = g_Weff + 0 * 4 * CC;
    const float* WeR = g_Weff + 1 * 4 * CC;
#pragma unroll
    for (int i = 0; i < 4; ++i) {
        int m = m0 + ty * 4 + i;
        if (m >= NN) continue;
        float xa0 = g_agg[m * 48 + t * 4 + 0];
        float xa1 = g_agg[m * 48 + t * 4 + 1];
        float xa2 = g_agg[m * 48 + t * 4 + 2];
        float xa3 = g_agg[m * 48 + t * 4 + 3];
#pragma unroll
        for (int j = 0; j < 4; ++j) {
            int c = n0 + tx * 4 + j;
            size_t idx = (size_t)m * CC + c;
            float vz = az[i][j] + g_beff[0 * CC + c]
                     + xa0 * WeZ[0 * CC + c] + xa1 * WeZ[1 * CC + c]
                     + xa2 * WeZ[2 * CC + c] + xa3 * WeZ[3 * CC + c];
            float z = 1.0f / (1.0f + expf(-vz));
            g_Z[idx] = z;
            float vr = ar[i][j] + g_beff[1 * CC + c]
                     + xa0 * WeR[0 * CC + c] + xa1 * WeR[1 * CC + c]
                     + xa2 * WeR[2 * CC + c] + xa3 * WeR[3 * CC + c];
            float r = 1.0f / (1.0f + expf(-vr));
            g_HR[idx] = g_H[idx] * r;
        }
    }
}

// ht = tanh(Xa@WeffH + HR@WhL_bot + beffH); Hn = z*H + (1-z)*ht; H=Hn; ACC += p*Hn
__global__ __launch_bounds__(256) void gemm_h_kernel(const float* __restrict__ Whl, int t) {
    __shared__ float As[BK][BM + 1];
    __shared__ float Bs[BK][BN];
    int tid = threadIdx.x;
    int tx = tid & 15, ty = tid >> 4;
    int m0 = blockIdx.x * BM;
    int n0 = blockIdx.y * BN;
    const float* BP = Whl + CC * CC;

    float ac[4][4];
#pragma unroll
    for (int i = 0; i < 4; ++i)
#pragma unroll
        for (int j = 0; j < 4; ++j) ac[i][j] = 0.f;

    int lr = tid >> 3;
    int lc = (tid & 7) << 2;
    int brw = tid >> 4;
    int bcc = (tid & 15) << 2;

    for (int k0 = 0; k0 < CC; k0 += BK) {
#pragma unroll
        for (int it = 0; it < 2; ++it) {
            int m = m0 + lr + it * 32;
            float4 v = make_float4(0.f, 0.f, 0.f, 0.f);
            if (m < NN) v = *(const float4*)(g_HR + (size_t)m * CC + k0 + lc);
            As[lc + 0][lr + it * 32] = v.x;
            As[lc + 1][lr + it * 32] = v.y;
            As[lc + 2][lr + it * 32] = v.z;
            As[lc + 3][lr + it * 32] = v.w;
        }
#pragma unroll
        for (int it = 0; it < 2; ++it) {
            int kk = brw + it * 16;
            *(float4*)&Bs[kk][bcc] = *(const float4*)(BP + (size_t)(k0 + kk) * CC + n0 + bcc);
        }
        __syncthreads();
#pragma unroll
        for (int kk = 0; kk < BK; ++kk) {
            float a[4];
#pragma unroll
            for (int i = 0; i < 4; ++i) a[i] = As[kk][ty * 4 + i];
            float4 b4 = *(float4*)&Bs[kk][tx * 4];
#pragma unroll
            for (int i = 0; i < 4; ++i) {
                ac[i][0] += a[i] * b4.x; ac[i][1] += a[i] * b4.y;
                ac[i][2] += a[i] * b4.z; ac[i][3] += a[i] * b4.w;
            }
        }
        __syncthreads();
    }

    const float* WeH = g_Weff + 2 * 4 * CC;
    float p = g_probs[t];
#pragma unroll
    for (int i = 0; i < 4; ++i) {
        int m = m0 + ty * 4 + i;
        if (m >= NN) continue;
        float xa0 = g_agg[m * 48 + t * 4 + 0];
        float xa1 = g_agg[m * 48 + t * 4 + 1];
        float xa2 = g_agg[m * 48 + t * 4 + 2];
        float xa3 = g_agg[m * 48 + t * 4 + 3];
#pragma unroll
        for (int j = 0; j < 4; ++j) {
            int c = n0 + tx * 4 + j;
            size_t idx = (size_t)m * CC + c;
            float v = ac[i][j] + g_beff[2 * CC + c]
                    + xa0 * WeH[0 * CC + c] + xa1 * WeH[1 * CC + c]
                    + xa2 * WeH[2 * CC + c] + xa3 * WeH[3 * CC + c];
            float ht = tanhf(v);
            float z = g_Z[idx];
            float Hn = z * g_H[idx] + (1.0f - z) * ht;
            g_H[idx] = Hn;
            g_ACC[idx] += p * Hn;
        }
    }
}

// h1 = relu( relu(ACC) @ W1 + b1 )   [N,512]@[512,256]
__global__ __launch_bounds__(256) void head1_kernel(const float* __restrict__ W1,
                                                    const float* __restrict__ b1) {
    __shared__ float As[BK][BM + 1];
    __shared__ float Bs[BK][BN];
    int tid = threadIdx.x;
    int tx = tid & 15, ty = tid >> 4;
    int m0 = blockIdx.x * BM;
    int n0 = blockIdx.y * BN;

    float ac[4][4];
#pragma unroll
    for (int i = 0; i < 4; ++i)
#pragma unroll
        for (int j = 0; j < 4; ++j) ac[i][j] = 0.f;

    int lr = tid >> 3;
    int lc = (tid & 7) << 2;
    int brw = tid >> 4;
    int bcc = (tid & 15) << 2;

    for (int k0 = 0; k0 < CC; k0 += BK) {
#pragma unroll
        for (int it = 0; it < 2; ++it) {
            int m = m0 + lr + it * 32;
            float4 v = make_float4(0.f, 0.f, 0.f, 0.f);
            if (m < NN) v = *(const float4*)(g_ACC + (size_t)m * CC + k0 + lc);
            As[lc + 0][lr + it * 32] = fmaxf(v.x, 0.f);
            As[lc + 1][lr + it * 32] = fmaxf(v.y, 0.f);
            As[lc + 2][lr + it * 32] = fmaxf(v.z, 0.f);
            As[lc + 3][lr + it * 32] = fmaxf(v.w, 0.f);
        }
#pragma unroll
        for (int it = 0; it < 2; ++it) {
            int kk = brw + it * 16;
            *(float4*)&Bs[kk][bcc] = *(const float4*)(W1 + (size_t)(k0 + kk) * HIDN + n0 + bcc);
        }
        __syncthreads();
#pragma unroll
        for (int kk = 0; kk < BK; ++kk) {
            float a[4];
#pragma unroll
            for (int i = 0; i < 4; ++i) a[i] = As[kk][ty * 4 + i];
            float4 b4 = *(float4*)&Bs[kk][tx * 4];
#pragma unroll
            for (int i = 0; i < 4; ++i) {
                ac[i][0] += a[i] * b4.x; ac[i][1] += a[i] * b4.y;
                ac[i][2] += a[i] * b4.z; ac[i][3] += a[i] * b4.w;
            }
        }
        __syncthreads();
    }
#pragma unroll
    for (int i = 0; i < 4; ++i) {
        int m = m0 + ty * 4 + i;
        if (m >= NN) continue;
#pragma unroll
        for (int j = 0; j < 4; ++j) {
            int c = n0 + tx * 4 + j;
            g_h1[(size_t)m * HIDN + c] = fmaxf(ac[i][j] + b1[c], 0.f);
        }
    }
}

// out_h = h1 @ W2 + b2   [N,256]@[256,12]
__global__ void head2_kernel(const float* __restrict__ W2, const float* __restrict__ b2,
                             float* __restrict__ out) {
    int idx = blockIdx.x * blockDim.x + threadIdx.x;
    if (idx >= NN * OUTD) return;
    int n = idx / OUTD;
    int o = idx % OUTD;
    float s = b2[o];
    const float* hrow = g_h1 + (size_t)n * HIDN;
#pragma unroll 8
    for (int k = 0; k < HIDN; ++k) s += hrow[k] * W2[k * OUTD + o];
    out[idx] = s;
}

__global__ void copy_acc_kernel(float* __restrict__ out) {
    int i = blockIdx.x * blockDim.x + threadIdx.x;
    if (i < NN * CC) out[NN * OUTD + i] = g_ACC[i];
}

// ---------------- launch ----------------
extern "C" void kernel_launch(void* const* d_in, const int* in_sizes, int n_in,
                              void* d_out, int out_size) {
    const float* x   = (const float*)d_in[0];
    const int*   ei  = (const int*)d_in[1];
    const float* ea  = (const float*)d_in[2];
    const float* att = (const float*)d_in[3];
    const float* Wzg = (const float*)d_in[4];  const float* bzg = (const float*)d_in[5];
    const float* Wzl = (const float*)d_in[6];  const float* bzl = (const float*)d_in[7];
    const float* Wrg = (const float*)d_in[8];  const float* brg = (const float*)d_in[9];
    const float* Wrl = (const float*)d_in[10]; const float* brl = (const float*)d_in[11];
    const float* Whg = (const float*)d_in[12]; const float* bhg = (const float*)d_in[13];
    const float* Whl = (const float*)d_in[14]; const float* bhl = (const float*)d_in[15];
    const float* W1  = (const float*)d_in[16]; const float* b1  = (const float*)d_in[17];
    const float* W2  = (const float*)d_in[18]; const float* b2  = (const float*)d_in[19];
    float* out = (float*)d_out;

    init_deg_kernel<<<(NN + 255) / 256, 256>>>();
    deg_edges_kernel<<<(EE + 255) / 256, 256>>>(ei, ea);
    dinv_kernel<<<(NN + 255) / 256, 256>>>();
    agg_init_kernel<<<(NN * 48 + 255) / 256, 256>>>(x);
    {
        long long tot = (long long)EE * 48;
        int blocks = (int)((tot + 255) / 256);
        agg_edges_kernel<<<blocks, 256>>>(x, ei, ea);
    }
    weff_kernel<<<10, 256>>>(Wzg, bzg, Wzl, bzl, 0);
    weff_kernel<<<10, 256>>>(Wrg, brg, Wrl, brl, 1);
    weff_kernel<<<10, 256>>>(Whg, bhg, Whl, bhl, 2);
    softmax_att_kernel<<<1, 32>>>(att);
    zero_HA_kernel<<<(NN * CC + 255) / 256, 256>>>();

    dim3 gz((NN + BM - 1) / BM, CC / BN);
    for (int t = 0; t < TT; ++t) {
        gemm_zr_kernel<<<gz, 256>>>(Wzl, Wrl, t);
        gemm_h_kernel<<<gz, 256>>>(Whl, t);
    }
    dim3 gh((NN + BM - 1) / BM, HIDN / BN);
    head1_kernel<<<gh, 256>>>(W1, b1);
    head2_kernel<<<(NN * OUTD + 255) / 256, 256>>>(W2, b2, out);
    copy_acc_kernel<<<(NN * CC + 255) / 256, 256>>>(out);
}

// round 2
// speedup vs baseline: 1.7013x; 1.7013x over previous
#include <cuda_runtime.h>
#include <math.h>

#define NN 10000
#define EE 160000
#define FF 4
#define TT 12
#define CC 512
#define HIDN 256
#define OUTD 12

// ---------------- scratch ----------------
__device__ float g_deg[NN];
__device__ float g_dinv[NN];
__device__ float g_agg[NN * FF * TT];    // [n][t*4+f]
__device__ float g_Weff[3 * FF * CC];    // [gate][f][c]
__device__ float g_beff[3 * CC];
__device__ float g_probs[TT];
__device__ float g_H[NN * CC];
__device__ float g_ACC[NN * CC];
__device__ float g_Z[NN * CC];
__device__ float g_HR[NN * CC];
__device__ float g_h1[NN * HIDN];
__device__ float g_Bzr[CC * 2 * CC];     // [k][n] n<512: Wzl_bot, else Wrl_bot (tf32-rounded)
__device__ float g_Bh[CC * CC];          // Whl bottom rows (tf32-rounded)

__device__ __forceinline__ unsigned f2tf(float f) {
    unsigned u; asm("cvt.rna.tf32.f32 %0, %1;" : "=r"(u) : "f"(f)); return u;
}

__device__ __forceinline__ void mma_tf32(float* c, const unsigned* a, const unsigned* b) {
    asm volatile(
        "mma.sync.aligned.m16n8k8.row.col.f32.tf32.tf32.f32 "
        "{%0,%1,%2,%3}, {%4,%5,%6,%7}, {%8,%9}, {%0,%1,%2,%3};\n"
        : "+f"(c[0]), "+f"(c[1]), "+f"(c[2]), "+f"(c[3])
        : "r"(a[0]), "r"(a[1]), "r"(a[2]), "r"(a[3]), "r"(b[0]), "r"(b[1]));
}

// ---------------- prep ----------------
__global__ void init_deg_kernel() {
    int i = blockIdx.x * blockDim.x + threadIdx.x;
    if (i < NN) g_deg[i] = 1.0f;
}
__global__ void deg_edges_kernel(const int* __restrict__ ei, const float* __restrict__ ea) {
    int e = blockIdx.x * blockDim.x + threadIdx.x;
    if (e < EE) atomicAdd(&g_deg[ei[EE + e]], ea[e]);
}
__global__ void dinv_kernel() {
    int i = blockIdx.x * blockDim.x + threadIdx.x;
    if (i < NN) g_dinv[i] = rsqrtf(fmaxf(g_deg[i], 1e-12f));
}
__global__ void agg_init_kernel(const float* __restrict__ x) {
    int idx = blockIdx.x * blockDim.x + threadIdx.x;
    if (idx >= NN * 48) return;
    int n = idx / 48, k = idx % 48, t = k >> 2, f = k & 3;
    float di = g_dinv[n];
    g_agg[idx] = di * di * x[n * 48 + f * 12 + t];
}
__global__ void agg_edges_kernel(const float* __restrict__ x,
                                 const int* __restrict__ ei,
                                 const float* __restrict__ ea) {
    long long idx = (long long)blockIdx.x * blockDim.x + threadIdx.x;
    if (idx >= (long long)EE * 48) return;
    int e = (int)(idx / 48), k = (int)(idx % 48), t = k >> 2, f = k & 3;
    int s = ei[e], d = ei[EE + e];
    float nrm = g_dinv[s] * ea[e] * g_dinv[d];
    atomicAdd(&g_agg[(long long)d * 48 + k], nrm * x[s * 48 + f * 12 + t]);
}
__global__ void weff_kernel(const float* __restrict__ Wg, const float* __restrict__ bg,
                            const float* __restrict__ Wl, const float* __restrict__ bl,
                            int gate) {
    int idx = blockIdx.x * blockDim.x + threadIdx.x;
    if (idx >= 5 * CC) return;
    int row = idx / CC, c = idx % CC;
    if (row < 4) {
        float s = 0.f;
        for (int k = 0; k < CC; ++k) s += Wg[row * CC + k] * Wl[k * CC + c];
        g_Weff[gate * 4 * CC + row * CC + c] = s;
    } else {
        float s = bl[c];
        for (int k = 0; k < CC; ++k) s += bg[k] * Wl[k * CC + c];
        g_beff[gate * CC + c] = s;
    }
}
__global__ void softmax_att_kernel(const float* __restrict__ att) {
    if (threadIdx.x == 0 && blockIdx.x == 0) {
        float m = -1e30f;
        for (int t = 0; t < TT; ++t) m = fmaxf(m, att[t]);
        float s = 0.f, e[TT];
        for (int t = 0; t < TT; ++t) { e[t] = expf(att[t] - m); s += e[t]; }
        float inv = 1.0f / s;
        for (int t = 0; t < TT; ++t) g_probs[t] = e[t] * inv;
    }
}
__global__ void zero_HA_kernel() {
    int i = blockIdx.x * blockDim.x + threadIdx.x;
    if (i < NN * CC) { g_H[i] = 0.f; g_ACC[i] = 0.f; }
}
__global__ void prep_Bzr_kernel(const float* __restrict__ Wzl, const float* __restrict__ Wrl) {
    int idx = blockIdx.x * blockDim.x + threadIdx.x;
    if (idx >= CC * 2 * CC) return;
    int k = idx >> 10, n = idx & 1023;
    float v = (n < CC) ? Wzl[CC * CC + k * CC + n] : Wrl[CC * CC + k * CC + (n - CC)];
    g_Bzr[idx] = __uint_as_float(f2tf(v));
}
__global__ void prep_Bh_kernel(const float* __restrict__ Whl) {
    int idx = blockIdx.x * blockDim.x + threadIdx.x;
    if (idx >= CC * CC) return;
    g_Bh[idx] = __uint_as_float(f2tf(Whl[CC * CC + idx]));
}

// ---------------- tensor-core GEMM kernels ----------------
#define SA 133
#define SB 136

// z & r fused GEMM: [N,512] @ [512,1024], epilogue -> g_Z, g_HR
__global__ __launch_bounds__(256, 2) void gemm_zr_tc(int t) {
    __shared__ unsigned As[32 * SA];
    __shared__ unsigned Bs[32 * SB];
    const int tid = threadIdx.x;
    const int lane = tid & 31, warp = tid >> 5;
    const int wm = warp & 3, wn = warp >> 2;
    const int g = lane >> 2, tig = lane & 3;
    const int m0 = blockIdx.x * 128;
    const int n0 = blockIdx.y * 128;

    float c[2][8][4];
#pragma unroll
    for (int i = 0; i < 2; ++i)
#pragma unroll
        for (int j = 0; j < 8; ++j)
#pragma unroll
            for (int q = 0; q < 4; ++q) c[i][j][q] = 0.f;

    const int arow = tid >> 3;
    const int acg = (tid & 7) * 4;
    const int bc4 = (tid & 31) * 4;
    const int bkr = tid >> 5;

    for (int k0 = 0; k0 < CC; k0 += 32) {
#pragma unroll
        for (int it = 0; it < 4; ++it) {
            int mloc = arow + it * 32;
            int m = m0 + mloc;
            float4 v = make_float4(0.f, 0.f, 0.f, 0.f);
            if (m < NN) v = *(const float4*)(g_H + (size_t)m * CC + k0 + acg);
            As[(acg + 0) * SA + mloc] = f2tf(v.x);
            As[(acg + 1) * SA + mloc] = f2tf(v.y);
            As[(acg + 2) * SA + mloc] = f2tf(v.z);
            As[(acg + 3) * SA + mloc] = f2tf(v.w);
        }
#pragma unroll
        for (int it = 0; it < 4; ++it) {
            int k = bkr + it * 8;
            float4 v = *(const float4*)(g_Bzr + (size_t)(k0 + k) * 1024 + n0 + bc4);
            *(float4*)((float*)&Bs[k * SB + bc4]) = v;
        }
        __syncthreads();
#pragma unroll
        for (int kc = 0; kc < 4; ++kc) {
            const int kb = kc * 8;
            unsigned a[2][4], b[8][2];
#pragma unroll
            for (int ms = 0; ms < 2; ++ms) {
                int mb = wm * 32 + ms * 16 + g;
                a[ms][0] = As[(kb + tig) * SA + mb];
                a[ms][1] = As[(kb + tig) * SA + mb + 8];
                a[ms][2] = As[(kb + tig + 4) * SA + mb];
                a[ms][3] = As[(kb + tig + 4) * SA + mb + 8];
            }
#pragma unroll
            for (int ns = 0; ns < 8; ++ns) {
                int nb = wn * 64 + ns * 8 + g;
                b[ns][0] = Bs[(kb + tig) * SB + nb];
                b[ns][1] = Bs[(kb + tig + 4) * SB + nb];
            }
#pragma unroll
            for (int ms = 0; ms < 2; ++ms)
#pragma unroll
                for (int ns = 0; ns < 8; ++ns) mma_tf32(c[ms][ns], a[ms], b[ns]);
        }
        __syncthreads();
    }

    // epilogue
#pragma unroll
    for (int ms = 0; ms < 2; ++ms) {
#pragma unroll
        for (int half = 0; half < 2; ++half) {
            int m = m0 + wm * 32 + ms * 16 + g + half * 8;
            if (m >= NN) continue;
            const float* ag = g_agg + m * 48 + t * 4;
            float xa0 = ag[0], xa1 = ag[1], xa2 = ag[2], xa3 = ag[3];
#pragma unroll
            for (int ns = 0; ns < 8; ++ns) {
                int ncol = n0 + wn * 64 + ns * 8 + tig * 2;
#pragma unroll
                for (int j = 0; j < 2; ++j) {
                    int nc = ncol + j;
                    float acc = c[ms][ns][half * 2 + j];
                    int gate = nc >> 9;
                    int ci = nc & 511;
                    const float* We = g_Weff + gate * 4 * CC;
                    float val = acc + g_beff[gate * CC + ci]
                              + xa0 * We[0 * CC + ci] + xa1 * We[1 * CC + ci]
                              + xa2 * We[2 * CC + ci] + xa3 * We[3 * CC + ci];
                    float s = 1.0f / (1.0f + expf(-val));
                    size_t idx = (size_t)m * CC + ci;
                    if (gate == 0) g_Z[idx] = s;
                    else g_HR[idx] = g_H[idx] * s;
                }
            }
        }
    }
}

// h GEMM: HR @ [512,512], epilogue -> H, ACC
__global__ __launch_bounds__(256, 2) void gemm_h_tc(int t) {
    __shared__ unsigned As[32 * SA];
    __shared__ unsigned Bs[32 * SB];
    const int tid = threadIdx.x;
    const int lane = tid & 31, warp = tid >> 5;
    const int wm = warp & 3, wn = warp >> 2;
    const int g = lane >> 2, tig = lane & 3;
    const int m0 = blockIdx.x * 128;
    const int n0 = blockIdx.y * 128;

    float c[2][8][4];
#pragma unroll
    for (int i = 0; i < 2; ++i)
#pragma unroll
        for (int j = 0; j < 8; ++j)
#pragma unroll
            for (int q = 0; q < 4; ++q) c[i][j][q] = 0.f;

    const int arow = tid >> 3;
    const int acg = (tid & 7) * 4;
    const int bc4 = (tid & 31) * 4;
    const int bkr = tid >> 5;

    for (int k0 = 0; k0 < CC; k0 += 32) {
#pragma unroll
        for (int it = 0; it < 4; ++it) {
            int mloc = arow + it * 32;
            int m = m0 + mloc;
            float4 v = make_float4(0.f, 0.f, 0.f, 0.f);
            if (m < NN) v = *(const float4*)(g_HR + (size_t)m * CC + k0 + acg);
            As[(acg + 0) * SA + mloc] = f2tf(v.x);
            As[(acg + 1) * SA + mloc] = f2tf(v.y);
            As[(acg + 2) * SA + mloc] = f2tf(v.z);
            As[(acg + 3) * SA + mloc] = f2tf(v.w);
        }
#pragma unroll
        for (int it = 0; it < 4; ++it) {
            int k = bkr + it * 8;
            float4 v = *(const float4*)(g_Bh + (size_t)(k0 + k) * CC + n0 + bc4);
            *(float4*)((float*)&Bs[k * SB + bc4]) = v;
        }
        __syncthreads();
#pragma unroll
        for (int kc = 0; kc < 4; ++kc) {
            const int kb = kc * 8;
            unsigned a[2][4], b[8][2];
#pragma unroll
            for (int ms = 0; ms < 2; ++ms) {
                int mb = wm * 32 + ms * 16 + g;
                a[ms][0] = As[(kb + tig) * SA + mb];
                a[ms][1] = As[(kb + tig) * SA + mb + 8];
                a[ms][2] = As[(kb + tig + 4) * SA + mb];
                a[ms][3] = As[(kb + tig + 4) * SA + mb + 8];
            }
#pragma unroll
            for (int ns = 0; ns < 8; ++ns) {
                int nb = wn * 64 + ns * 8 + g;
                b[ns][0] = Bs[(kb + tig) * SB + nb];
                b[ns][1] = Bs[(kb + tig + 4) * SB + nb];
            }
#pragma unroll
            for (int ms = 0; ms < 2; ++ms)
#pragma unroll
                for (int ns = 0; ns < 8; ++ns) mma_tf32(c[ms][ns], a[ms], b[ns]);
        }
        __syncthreads();
    }

    const float* WeH = g_Weff + 2 * 4 * CC;
    float p = g_probs[t];
#pragma unroll
    for (int ms = 0; ms < 2; ++ms) {
#pragma unroll
        for (int half = 0; half < 2; ++half) {
            int m = m0 + wm * 32 + ms * 16 + g + half * 8;
            if (m >= NN) continue;
            const float* ag = g_agg + m * 48 + t * 4;
            float xa0 = ag[0], xa1 = ag[1], xa2 = ag[2], xa3 = ag[3];
#pragma unroll
            for (int ns = 0; ns < 8; ++ns) {
                int ncol = n0 + wn * 64 + ns * 8 + tig * 2;
#pragma unroll
                for (int j = 0; j < 2; ++j) {
                    int ci = ncol + j;
                    float acc = c[ms][ns][half * 2 + j];
                    float val = acc + g_beff[2 * CC + ci]
                              + xa0 * WeH[0 * CC + ci] + xa1 * WeH[1 * CC + ci]
                              + xa2 * WeH[2 * CC + ci] + xa3 * WeH[3 * CC + ci];
                    float ht = tanhf(val);
                    size_t idx = (size_t)m * CC + ci;
                    float z = g_Z[idx];
                    float Hn = z * g_H[idx] + (1.0f - z) * ht;
                    g_H[idx] = Hn;
                    g_ACC[idx] += p * Hn;
                }
            }
        }
    }
}

// head1: relu(ACC) @ W1 (+b1, relu) -> g_h1  [N,512]x[512,256]
__global__ __launch_bounds__(256, 2) void head1_tc(const float* __restrict__ W1,
                                                   const float* __restrict__ b1) {
    __shared__ unsigned As[32 * SA];
    __shared__ unsigned Bs[32 * SB];
    const int tid = threadIdx.x;
    const int lane = tid & 31, warp = tid >> 5;
    const int wm = warp & 3, wn = warp >> 2;
    const int g = lane >> 2, tig = lane & 3;
    const int m0 = blockIdx.x * 128;
    const int n0 = blockIdx.y * 128;

    float c[2][8][4];
#pragma unroll
    for (int i = 0; i < 2; ++i)
#pragma unroll
        for (int j = 0; j < 8; ++j)
#pragma unroll
            for (int q = 0; q < 4; ++q) c[i][j][q] = 0.f;

    const int arow = tid >> 3;
    const int acg = (tid & 7) * 4;
    const int bc4 = (tid & 31) * 4;
    const int bkr = tid >> 5;

    for (int k0 = 0; k0 < CC; k0 += 32) {
#pragma unroll
        for (int it = 0; it < 4; ++it) {
            int mloc = arow + it * 32;
            int m = m0 + mloc;
            float4 v = make_float4(0.f, 0.f, 0.f, 0.f);
            if (m < NN) v = *(const float4*)(g_ACC + (size_t)m * CC + k0 + acg);
            As[(acg + 0) * SA + mloc] = f2tf(fmaxf(v.x, 0.f));
            As[(acg + 1) * SA + mloc] = f2tf(fmaxf(v.y, 0.f));
            As[(acg + 2) * SA + mloc] = f2tf(fmaxf(v.z, 0.f));
            As[(acg + 3) * SA + mloc] = f2tf(fmaxf(v.w, 0.f));
        }
#pragma unroll
        for (int it = 0; it < 4; ++it) {
            int k = bkr + it * 8;
            float4 v = *(const float4*)(W1 + (size_t)(k0 + k) * HIDN + n0 + bc4);
            Bs[k * SB + bc4 + 0] = f2tf(v.x);
            Bs[k * SB + bc4 + 1] = f2tf(v.y);
            Bs[k * SB + bc4 + 2] = f2tf(v.z);
            Bs[k * SB + bc4 + 3] = f2tf(v.w);
        }
        __syncthreads();
#pragma unroll
        for (int kc = 0; kc < 4; ++kc) {
            const int kb = kc * 8;
            unsigned a[2][4], b[8][2];
#pragma unroll
            for (int ms = 0; ms < 2; ++ms) {
                int mb = wm * 32 + ms * 16 + g;
                a[ms][0] = As[(kb + tig) * SA + mb];
                a[ms][1] = As[(kb + tig) * SA + mb + 8];
                a[ms][2] = As[(kb + tig + 4) * SA + mb];
                a[ms][3] = As[(kb + tig + 4) * SA + mb + 8];
            }
#pragma unroll
            for (int ns = 0; ns < 8; ++ns) {
                int nb = wn * 64 + ns * 8 + g;
                b[ns][0] = Bs[(kb + tig) * SB + nb];
                b[ns][1] = Bs[(kb + tig + 4) * SB + nb];
            }
#pragma unroll
            for (int ms = 0; ms < 2; ++ms)
#pragma unroll
                for (int ns = 0; ns < 8; ++ns) mma_tf32(c[ms][ns], a[ms], b[ns]);
        }
        __syncthreads();
    }

#pragma unroll
    for (int ms = 0; ms < 2; ++ms) {
#pragma unroll
        for (int half = 0; half < 2; ++half) {
            int m = m0 + wm * 32 + ms * 16 + g + half * 8;
            if (m >= NN) continue;
#pragma unroll
            for (int ns = 0; ns < 8; ++ns) {
                int ncol = n0 + wn * 64 + ns * 8 + tig * 2;
#pragma unroll
                for (int j = 0; j < 2; ++j) {
                    int ci = ncol + j;
                    float v = fmaxf(c[ms][ns][half * 2 + j] + b1[ci], 0.f);
                    g_h1[(size_t)m * HIDN + ci] = v;
                }
            }
        }
    }
}

__global__ void head2_kernel(const float* __restrict__ W2, const float* __restrict__ b2,
                             float* __restrict__ out) {
    int idx = blockIdx.x * blockDim.x + threadIdx.x;
    if (idx >= NN * OUTD) return;
    int n = idx / OUTD, o = idx % OUTD;
    float s = b2[o];
    const float* hrow = g_h1 + (size_t)n * HIDN;
#pragma unroll 8
    for (int k = 0; k < HIDN; ++k) s += hrow[k] * W2[k * OUTD + o];
    out[idx] = s;
}

__global__ void copy_acc_kernel(float* __restrict__ out) {
    int i = blockIdx.x * blockDim.x + threadIdx.x;
    if (i < NN * CC) out[NN * OUTD + i] = g_ACC[i];
}

// ---------------- launch ----------------
extern "C" void kernel_launch(void* const* d_in, const int* in_sizes, int n_in,
                              void* d_out, int out_size) {
    const float* x   = (const float*)d_in[0];
    const int*   ei  = (const int*)d_in[1];
    const float* ea  = (const float*)d_in[2];
    const float* att = (const float*)d_in[3];
    const float* Wzg = (const float*)d_in[4];  const float* bzg = (const float*)d_in[5];
    const float* Wzl = (const float*)d_in[6];  const float* bzl = (const float*)d_in[7];
    const float* Wrg = (const float*)d_in[8];  const float* brg = (const float*)d_in[9];
    const float* Wrl = (const float*)d_in[10]; const float* brl = (const float*)d_in[11];
    const float* Whg = (const float*)d_in[12]; const float* bhg = (const float*)d_in[13];
    const float* Whl = (const float*)d_in[14]; const float* bhl = (const float*)d_in[15];
    const float* W1  = (const float*)d_in[16]; const float* b1  = (const float*)d_in[17];
    const float* W2  = (const float*)d_in[18]; const float* b2  = (const float*)d_in[19];
    float* out = (float*)d_out;

    init_deg_kernel<<<(NN + 255) / 256, 256>>>();
    deg_edges_kernel<<<(EE + 255) / 256, 256>>>(ei, ea);
    dinv_kernel<<<(NN + 255) / 256, 256>>>();
    agg_init_kernel<<<(NN * 48 + 255) / 256, 256>>>(x);
    {
        long long tot = (long long)EE * 48;
        int blocks = (int)((tot + 255) / 256);
        agg_edges_kernel<<<blocks, 256>>>(x, ei, ea);
    }
    weff_kernel<<<10, 256>>>(Wzg, bzg, Wzl, bzl, 0);
    weff_kernel<<<10, 256>>>(Wrg, brg, Wrl, brl, 1);
    weff_kernel<<<10, 256>>>(Whg, bhg, Whl, bhl, 2);
    softmax_att_kernel<<<1, 32>>>(att);
    zero_HA_kernel<<<(NN * CC + 255) / 256, 256>>>();
    prep_Bzr_kernel<<<(CC * 2 * CC + 255) / 256, 256>>>(Wzl, Wrl);
    prep_Bh_kernel<<<(CC * CC + 255) / 256, 256>>>(Whl);

    dim3 gzr((NN + 127) / 128, (2 * CC) / 128);
    dim3 gh((NN + 127) / 128, CC / 128);
    for (int t = 0; t < TT; ++t) {
        gemm_zr_tc<<<gzr, 256>>>(t);
        gemm_h_tc<<<gh, 256>>>(t);
    }
    dim3 g1((NN + 127) / 128, HIDN / 128);
    head1_tc<<<g1, 256>>>(W1, b1);
    head2_kernel<<<(NN * OUTD + 255) / 256, 256>>>(W2, b2, out);
    copy_acc_kernel<<<(NN * CC + 255) / 256, 256>>>(out);
}

// round 8
// speedup vs baseline: 2.7298x; 1.6046x over previous
#include <cuda_runtime.h>
#include <cuda_fp16.h>
#include <math.h>
#include <stdint.h>

#define NN 10000
#define EE 160000
#define TT 12
#define CC 512
#define HIDN 256
#define OUTD 12

// ---------------- scratch ----------------
__device__ __align__(128) float g_deg[NN];
__device__ __align__(128) float g_dinv[NN];
__device__ __align__(128) float g_agg[NN * 48];       // [n][t*4+f]
__device__ __align__(128) float g_Weff[3 * 4 * CC];   // [gate][f][c]
__device__ __align__(128) float g_beff[3 * CC];
__device__ float g_probs[TT];
__device__ __align__(128) float g_H[NN * CC];
__device__ __align__(128) float g_ACC[NN * CC];
__device__ __align__(128) float g_Z[NN * CC];
__device__ __align__(128) float g_HR[NN * CC];
__device__ __align__(128) float g_h1[NN * HIDN];
__device__ __align__(128) __half g_Bzr_h[1024 * CC];  // [n][k]; n<512: Wzl_bot col n, else Wrl_bot
__device__ __align__(128) __half g_Bh_h[CC * CC];     // [n][k]; Whl_bot transposed

// ---------------- helpers ----------------
__device__ __forceinline__ unsigned f2tf(float f) {
    unsigned u; asm("cvt.rna.tf32.f32 %0, %1;" : "=r"(u) : "f"(f)); return u;
}
__device__ __forceinline__ uint32_t s2u(const void* p) {
    uint32_t a;
    asm("{ .reg .u64 t; cvta.to.shared.u64 t, %1; cvt.u32.u64 %0, t; }" : "=r"(a) : "l"(p));
    return a;
}
__device__ __forceinline__ void cpa16(uint32_t dst, const void* src) {
    asm volatile("cp.async.cg.shared.global [%0], [%1], 16;" :: "r"(dst), "l"(src));
}
__device__ __forceinline__ void cpa_commit() { asm volatile("cp.async.commit_group;"); }
__device__ __forceinline__ void cpa_wait0() {
    asm volatile("cp.async.wait_group 0;" ::: "memory");
}
__device__ __forceinline__ uint32_t packh2(float lo, float hi) {
    __half2 h = __floats2half2_rn(lo, hi);
    return *(uint32_t*)&h;
}
__device__ __forceinline__ void mma_f16(float* c, const uint32_t* a, const uint32_t* b) {
    asm volatile(
        "mma.sync.aligned.m16n8k16.row.col.f32.f16.f16.f32 "
        "{%0,%1,%2,%3}, {%4,%5,%6,%7}, {%8,%9}, {%0,%1,%2,%3};\n"
        : "+f"(c[0]), "+f"(c[1]), "+f"(c[2]), "+f"(c[3])
        : "r"(a[0]), "r"(a[1]), "r"(a[2]), "r"(a[3]), "r"(b[0]), "r"(b[1]));
}
__device__ __forceinline__ void mma_tf32(float* c, const unsigned* a, const unsigned* b) {
    asm volatile(
        "mma.sync.aligned.m16n8k8.row.col.f32.tf32.tf32.f32 "
        "{%0,%1,%2,%3}, {%4,%5,%6,%7}, {%8,%9}, {%0,%1,%2,%3};\n"
        : "+f"(c[0]), "+f"(c[1]), "+f"(c[2]), "+f"(c[3])
        : "r"(a[0]), "r"(a[1]), "r"(a[2]), "r"(a[3]), "r"(b[0]), "r"(b[1]));
}

// ---------------- prep kernels ----------------
__global__ void init_deg_kernel() {
    int i = blockIdx.x * blockDim.x + threadIdx.x;
    if (i < NN) g_deg[i] = 1.0f;
}
__global__ void deg_edges_kernel(const int* __restrict__ ei, const float* __restrict__ ea) {
    int e = blockIdx.x * blockDim.x + threadIdx.x;
    if (e < EE) atomicAdd(&g_deg[ei[EE + e]], ea[e]);
}
__global__ void dinv_kernel() {
    int i = blockIdx.x * blockDim.x + threadIdx.x;
    if (i < NN) g_dinv[i] = rsqrtf(fmaxf(g_deg[i], 1e-12f));
}
__global__ void agg_init_kernel(const float* __restrict__ x) {
    int idx = blockIdx.x * blockDim.x + threadIdx.x;
    if (idx >= NN * 48) return;
    int n = idx / 48, k = idx % 48, t = k >> 2, f = k & 3;
    float di = g_dinv[n];
    g_agg[idx] = di * di * x[n * 48 + f * 12 + t];
}
__global__ void agg_edges_kernel(const float* __restrict__ x,
                                 const int* __restrict__ ei,
                                 const float* __restrict__ ea) {
    long long idx = (long long)blockIdx.x * blockDim.x + threadIdx.x;
    if (idx >= (long long)EE * 48) return;
    int e = (int)(idx / 48), k = (int)(idx % 48), t = k >> 2, f = k & 3;
    int s = ei[e], d = ei[EE + e];
    float nrm = g_dinv[s] * ea[e] * g_dinv[d];
    atomicAdd(&g_agg[(long long)d * 48 + k], nrm * x[s * 48 + f * 12 + t]);
}
__global__ void weff_kernel(const float* __restrict__ Wg, const float* __restrict__ bg,
                            const float* __restrict__ Wl, const float* __restrict__ bl,
                            int gate) {
    int idx = blockIdx.x * blockDim.x + threadIdx.x;
    if (idx >= 5 * CC) return;
    int row = idx / CC, c = idx % CC;
    if (row < 4) {
        float s = 0.f;
        for (int k = 0; k < CC; ++k) s += Wg[row * CC + k] * Wl[k * CC + c];
        g_Weff[gate * 4 * CC + row * CC + c] = s;
    } else {
        float s = bl[c];
        for (int k = 0; k < CC; ++k) s += bg[k] * Wl[k * CC + c];
        g_beff[gate * CC + c] = s;
    }
}
__global__ void softmax_att_kernel(const float* __restrict__ att) {
    if (threadIdx.x == 0 && blockIdx.x == 0) {
        float m = -1e30f;
        for (int t = 0; t < TT; ++t) m = fmaxf(m, att[t]);
        float s = 0.f, e[TT];
        for (int t = 0; t < TT; ++t) { e[t] = expf(att[t] - m); s += e[t]; }
        float inv = 1.0f / s;
        for (int t = 0; t < TT; ++t) g_probs[t] = e[t] * inv;
    }
}
__global__ void zero_HA_kernel() {
    int i = blockIdx.x * blockDim.x + threadIdx.x;
    if (i < NN * CC) { g_H[i] = 0.f; g_ACC[i] = 0.f; }
}
// weight bottom halves -> half, [n][k] layout
__global__ void prep_Bzr_h_kernel(const float* __restrict__ Wzl, const float* __restrict__ Wrl) {
    int idx = blockIdx.x * blockDim.x + threadIdx.x;
    if (idx >= 1024 * CC) return;
    int n = idx / CC, k = idx % CC;
    const float* W = (n < CC) ? Wzl : Wrl;
    g_Bzr_h[idx] = __float2half_rn(W[(CC + k) * CC + (n & (CC - 1))]);
}
__global__ void prep_Bh_h_kernel(const float* __restrict__ Whl) {
    int idx = blockIdx.x * blockDim.x + threadIdx.x;
    if (idx >= CC * CC) return;
    int n = idx / CC, k = idx % CC;
    g_Bh_h[idx] = __float2half_rn(Whl[(CC + k) * CC + n]);
}

// ---------------- fp16 tensor-core GEMM (double-buffered) ----------------
// Tile 128x128x32. SMEM layout: [row][k2] with row stride RS=20 half2 words.
#define RS 20

struct Frag {
    float c[2][8][4];
};

__device__ __forceinline__ void gemm_mainloop_f16(
    uint32_t (*As)[128 * RS], uint32_t (*Bs)[128 * RS],
    const float* __restrict__ Asrc, const __half* __restrict__ Bsrc,
    int m0, int n0, int tid, Frag& fr) {

    const int lane = tid & 31, warp = tid >> 5;
    const int wm = warp & 3, wn = warp >> 2;
    const int g = lane >> 2, tig = lane & 3;

#pragma unroll
    for (int i = 0; i < 2; ++i)
#pragma unroll
        for (int j = 0; j < 8; ++j)
#pragma unroll
            for (int q = 0; q < 4; ++q) fr.c[i][j][q] = 0.f;

    const int arow = tid >> 3;          // 0..31
    const int ach = tid & 7;            // k chunk of 4 floats
    const int brow = tid >> 2;          // 0..63
    const int bcc = tid & 3;            // 16B chunk (8 halfs)
    uint32_t sB0 = s2u(&Bs[0][0]);
    uint32_t sB1 = s2u(&Bs[1][0]);

    float4 pf[4];
    // prologue: stage k-tile 0 into buffer 0
#pragma unroll
    for (int it = 0; it < 4; ++it) {
        int row = arow + it * 32;
        int m = m0 + row;
        pf[it] = (m < NN) ? *(const float4*)(Asrc + (size_t)m * CC + ach * 4)
                          : make_float4(0.f, 0.f, 0.f, 0.f);
    }
#pragma unroll
    for (int it = 0; it < 4; ++it) {
        int row = arow + it * 32;
        As[0][row * RS + ach * 2 + 0] = packh2(pf[it].x, pf[it].y);
        As[0][row * RS + ach * 2 + 1] = packh2(pf[it].z, pf[it].w);
    }
#pragma unroll
    for (int it = 0; it < 2; ++it) {
        int row = brow + it * 64;
        cpa16(sB0 + (uint32_t)(row * (RS * 4) + bcc * 16),
              Bsrc + (size_t)(n0 + row) * CC + bcc * 8);
    }
    cpa_commit();

    int cur = 0;
    for (int kt = 0; kt < 16; ++kt) {
        int k0n = (kt + 1) * 32;
        if (kt < 15) {
#pragma unroll
            for (int it = 0; it < 4; ++it) {
                int row = arow + it * 32;
                int m = m0 + row;
                pf[it] = (m < NN) ? *(const float4*)(Asrc + (size_t)m * CC + k0n + ach * 4)
                                  : make_float4(0.f, 0.f, 0.f, 0.f);
            }
        }
        cpa_wait0();
        __syncthreads();

        const uint32_t* Ac = As[cur];
        const uint32_t* Bc = Bs[cur];
#pragma unroll
        for (int kc = 0; kc < 2; ++kc) {
            const int kb = kc * 8;
            uint32_t a[2][4], b[8][2];
#pragma unroll
            for (int ms = 0; ms < 2; ++ms) {
                int r = wm * 32 + ms * 16 + g;
                a[ms][0] = Ac[r * RS + kb + tig];
                a[ms][1] = Ac[(r + 8) * RS + kb + tig];
                a[ms][2] = Ac[r * RS + kb + tig + 4];
                a[ms][3] = Ac[(r + 8) * RS + kb + tig + 4];
            }
#pragma unroll
            for (int ns = 0; ns < 8; ++ns) {
                int n = wn * 64 + ns * 8 + g;
                b[ns][0] = Bc[n * RS + kb + tig];
                b[ns][1] = Bc[n * RS + kb + tig + 4];
            }
#pragma unroll
            for (int ms = 0; ms < 2; ++ms)
#pragma unroll
                for (int ns = 0; ns < 8; ++ns) mma_f16(fr.c[ms][ns], a[ms], b[ns]);
        }

        if (kt < 15) {
            int nb = cur ^ 1;
#pragma unroll
            for (int it = 0; it < 4; ++it) {
                int row = arow + it * 32;
                As[nb][row * RS + ach * 2 + 0] = packh2(pf[it].x, pf[it].y);
                As[nb][row * RS + ach * 2 + 1] = packh2(pf[it].z, pf[it].w);
            }
            uint32_t sBn = nb ? sB1 : sB0;
#pragma unroll
            for (int it = 0; it < 2; ++it) {
                int row = brow + it * 64;
                cpa16(sBn + (uint32_t)(row * (RS * 4) + bcc * 16),
                      Bsrc + (size_t)(n0 + row) * CC + k0n + bcc * 8);
            }
            cpa_commit();
        }
        cur ^= 1;
    }
}

// z & r fused: grid (79, 8); by<4 -> z gate, by>=4 -> r gate
__global__ __launch_bounds__(256) void gemm_zr_f16(int t) {
    __shared__ __align__(16) uint32_t As[2][128 * RS];
    __shared__ __align__(16) uint32_t Bs[2][128 * RS];
    const int tid = threadIdx.x;
    const int lane = tid & 31, warp = tid >> 5;
    const int wm = warp & 3, wn = warp >> 2;
    const int g = lane >> 2, tig = lane & 3;
    const int m0 = blockIdx.x * 128;
    const int n0 = blockIdx.y * 128;

    Frag fr;
    gemm_mainloop_f16(As, Bs, g_H, g_Bzr_h, m0, n0, tid, fr);

    int gate = n0 >> 9;
    int c0 = n0 & (CC - 1);
    const float* We = g_Weff + gate * 4 * CC;
    const float* be = g_beff + gate * CC;

#pragma unroll
    for (int ms = 0; ms < 2; ++ms) {
#pragma unroll
        for (int half = 0; half < 2; ++half) {
            int m = m0 + wm * 32 + ms * 16 + g + half * 8;
            if (m >= NN) continue;
            const float* ag = g_agg + (size_t)m * 48 + t * 4;
            float xa0 = ag[0], xa1 = ag[1], xa2 = ag[2], xa3 = ag[3];
            size_t rbase = (size_t)m * CC;
#pragma unroll
            for (int ns = 0; ns < 8; ++ns) {
                int ncol = c0 + wn * 64 + ns * 8 + tig * 2;
#pragma unroll
                for (int j = 0; j < 2; ++j) {
                    int ci = ncol + j;
                    float acc = fr.c[ms][ns][half * 2 + j];
                    float val = acc + be[ci]
                              + xa0 * We[ci] + xa1 * We[CC + ci]
                              + xa2 * We[2 * CC + ci] + xa3 * We[3 * CC + ci];
                    float s = 1.0f / (1.0f + expf(-val));
                    if (gate == 0) g_Z[rbase + ci] = s;
                    else g_HR[rbase + ci] = g_H[rbase + ci] * s;
                }
            }
        }
    }
}

// h gate: grid (79, 4)
__global__ __launch_bounds__(256) void gemm_h_f16(int t) {
    __shared__ __align__(16) uint32_t As[2][128 * RS];
    __shared__ __align__(16) uint32_t Bs[2][128 * RS];
    const int tid = threadIdx.x;
    const int lane = tid & 31, warp = tid >> 5;
    const int wm = warp & 3, wn = warp >> 2;
    const int g = lane >> 2, tig = lane & 3;
    const int m0 = blockIdx.x * 128;
    const int n0 = blockIdx.y * 128;

    Frag fr;
    gemm_mainloop_f16(As, Bs, g_HR, g_Bh_h, m0, n0, tid, fr);

    const float* We = g_Weff + 2 * 4 * CC;
    const float* be = g_beff + 2 * CC;
    float p = g_probs[t];

#pragma unroll
    for (int ms = 0; ms < 2; ++ms) {
#pragma unroll
        for (int half = 0; half < 2; ++half) {
            int m = m0 + wm * 32 + ms * 16 + g + half * 8;
            if (m >= NN) continue;
            const float* ag = g_agg + (size_t)m * 48 + t * 4;
            float xa0 = ag[0], xa1 = ag[1], xa2 = ag[2], xa3 = ag[3];
            size_t rbase = (size_t)m * CC;
#pragma unroll
            for (int ns = 0; ns < 8; ++ns) {
                int ncol = n0 + wn * 64 + ns * 8 + tig * 2;
#pragma unroll
                for (int j = 0; j < 2; ++j) {
                    int ci = ncol + j;
                    float acc = fr.c[ms][ns][half * 2 + j];
                    float val = acc + be[ci]
                              + xa0 * We[ci] + xa1 * We[CC + ci]
                              + xa2 * We[2 * CC + ci] + xa3 * We[3 * CC + ci];
                    float ht = tanhf(val);
                    float z = g_Z[rbase + ci];
                    float Hn = z * g_H[rbase + ci] + (1.0f - z) * ht;
                    g_H[rbase + ci] = Hn;
                    g_ACC[rbase + ci] += p * Hn;
                }
            }
        }
    }
}

// ---------------- head (tf32 mma.sync, known-good) ----------------
#define SA 133
#define SB 136
__global__ __launch_bounds__(256, 2) void head1_tc(const float* __restrict__ W1,
                                                   const float* __restrict__ b1) {
    __shared__ unsigned As[32 * SA];
    __shared__ unsigned Bs[32 * SB];
    const int tid = threadIdx.x;
    const int lane = tid & 31, warp = tid >> 5;
    const int wm = warp & 3, wn = warp >> 2;
    const int g = lane >> 2, tig = lane & 3;
    const int m0 = blockIdx.x * 128;
    const int n0 = blockIdx.y * 128;

    float c[2][8][4];
#pragma unroll
    for (int i = 0; i < 2; ++i)
#pragma unroll
        for (int j = 0; j < 8; ++j)
#pragma unroll
            for (int q = 0; q < 4; ++q) c[i][j][q] = 0.f;

    const int arow = tid >> 3;
    const int acg = (tid & 7) * 4;
    const int bc4 = (tid & 31) * 4;
    const int bkr = tid >> 5;

    for (int k0 = 0; k0 < CC; k0 += 32) {
#pragma unroll
        for (int it = 0; it < 4; ++it) {
            int mloc = arow + it * 32;
            int m = m0 + mloc;
            float4 v = make_float4(0.f, 0.f, 0.f, 0.f);
            if (m < NN) v = *(const float4*)(g_ACC + (size_t)m * CC + k0 + acg);
            As[(acg + 0) * SA + mloc] = f2tf(fmaxf(v.x, 0.f));
            As[(acg + 1) * SA + mloc] = f2tf(fmaxf(v.y, 0.f));
            As[(acg + 2) * SA + mloc] = f2tf(fmaxf(v.z, 0.f));
            As[(acg + 3) * SA + mloc] = f2tf(fmaxf(v.w, 0.f));
        }
#pragma unroll
        for (int it = 0; it < 4; ++it) {
            int k = bkr + it * 8;
            float4 v = *(const float4*)(W1 + (size_t)(k0 + k) * HIDN + n0 + bc4);
            Bs[k * SB + bc4 + 0] = f2tf(v.x);
            Bs[k * SB + bc4 + 1] = f2tf(v.y);
            Bs[k * SB + bc4 + 2] = f2tf(v.z);
            Bs[k * SB + bc4 + 3] = f2tf(v.w);
        }
        __syncthreads();
#pragma unroll
        for (int kc = 0; kc < 4; ++kc) {
            const int kb = kc * 8;
            unsigned a[2][4], b[8][2];
#pragma unroll
            for (int ms = 0; ms < 2; ++ms) {
                int mb = wm * 32 + ms * 16 + g;
                a[ms][0] = As[(kb + tig) * SA + mb];
                a[ms][1] = As[(kb + tig) * SA + mb + 8];
                a[ms][2] = As[(kb + tig + 4) * SA + mb];
                a[ms][3] = As[(kb + tig + 4) * SA + mb + 8];
            }
#pragma unroll
            for (int ns = 0; ns < 8; ++ns) {
                int nb = wn * 64 + ns * 8 + g;
                b[ns][0] = Bs[(kb + tig) * SB + nb];
                b[ns][1] = Bs[(kb + tig + 4) * SB + nb];
            }
#pragma unroll
            for (int ms = 0; ms < 2; ++ms)
#pragma unroll
                for (int ns = 0; ns < 8; ++ns) mma_tf32(c[ms][ns], a[ms], b[ns]);
        }
        __syncthreads();
    }
#pragma unroll
    for (int ms = 0; ms < 2; ++ms) {
#pragma unroll
        for (int half = 0; half < 2; ++half) {
            int m = m0 + wm * 32 + ms * 16 + g + half * 8;
            if (m >= NN) continue;
#pragma unroll
            for (int ns = 0; ns < 8; ++ns) {
                int ncol = n0 + wn * 64 + ns * 8 + tig * 2;
#pragma unroll
                for (int j = 0; j < 2; ++j) {
                    int ci = ncol + j;
                    float v = fmaxf(c[ms][ns][half * 2 + j] + b1[ci], 0.f);
                    g_h1[(size_t)m * HIDN + ci] = v;
                }
            }
        }
    }
}

__global__ void head2_kernel(const float* __restrict__ W2, const float* __restrict__ b2,
                             float* __restrict__ out) {
    int idx = blockIdx.x * blockDim.x + threadIdx.x;
    if (idx >= NN * OUTD) return;
    int n = idx / OUTD, o = idx % OUTD;
    float s = b2[o];
    const float* hrow = g_h1 + (size_t)n * HIDN;
#pragma unroll 8
    for (int k = 0; k < HIDN; ++k) s += hrow[k] * W2[k * OUTD + o];
    out[idx] = s;
}

__global__ void copy_acc_kernel(float* __restrict__ out) {
    int i = blockIdx.x * blockDim.x + threadIdx.x;
    if (i < NN * CC) out[NN * OUTD + i] = g_ACC[i];
}

// ---------------- launch ----------------
extern "C" void kernel_launch(void* const* d_in, const int* in_sizes, int n_in,
                              void* d_out, int out_size) {
    const float* x   = (const float*)d_in[0];
    const int*   ei  = (const int*)d_in[1];
    const float* ea  = (const float*)d_in[2];
    const float* att = (const float*)d_in[3];
    const float* Wzg = (const float*)d_in[4];  const float* bzg = (const float*)d_in[5];
    const float* Wzl = (const float*)d_in[6];  const float* bzl = (const float*)d_in[7];
    const float* Wrg = (const float*)d_in[8];  const float* brg = (const float*)d_in[9];
    const float* Wrl = (const float*)d_in[10]; const float* brl = (const float*)d_in[11];
    const float* Whg = (const float*)d_in[12]; const float* bhg = (const float*)d_in[13];
    const float* Whl = (const float*)d_in[14]; const float* bhl = (const float*)d_in[15];
    const float* W1  = (const float*)d_in[16]; const float* b1  = (const float*)d_in[17];
    const float* W2  = (const float*)d_in[18]; const float* b2  = (const float*)d_in[19];
    float* out = (float*)d_out;

    init_deg_kernel<<<(NN + 255) / 256, 256>>>();
    deg_edges_kernel<<<(EE + 255) / 256, 256>>>(ei, ea);
    dinv_kernel<<<(NN + 255) / 256, 256>>>();
    agg_init_kernel<<<(NN * 48 + 255) / 256, 256>>>(x);
    {
        long long tot = (long long)EE * 48;
        int blocks = (int)((tot + 255) / 256);
        agg_edges_kernel<<<blocks, 256>>>(x, ei, ea);
    }
    weff_kernel<<<10, 256>>>(Wzg, bzg, Wzl, bzl, 0);
    weff_kernel<<<10, 256>>>(Wrg, brg, Wrl, brl, 1);
    weff_kernel<<<10, 256>>>(Whg, bhg, Whl, bhl, 2);
    softmax_att_kernel<<<1, 32>>>(att);
    zero_HA_kernel<<<(NN * CC + 255) / 256, 256>>>();
    prep_Bzr_h_kernel<<<(1024 * CC + 255) / 256, 256>>>(Wzl, Wrl);
    prep_Bh_h_kernel<<<(CC * CC + 255) / 256, 256>>>(Whl);

    dim3 gzr((NN + 127) / 128, 1024 / 128);   // 79 x 8
    dim3 gh((NN + 127) / 128, CC / 128);      // 79 x 4
    for (int t = 0; t < TT; ++t) {
        gemm_zr_f16<<<gzr, 256>>>(t);
        gemm_h_f16<<<gh, 256>>>(t);
    }
    dim3 g1((NN + 127) / 128, HIDN / 128);
    head1_tc<<<g1, 256>>>(W1, b1);
    head2_kernel<<<(NN * OUTD + 255) / 256, 256>>>(W2, b2, out);
    copy_acc_kernel<<<(NN * CC + 255) / 256, 256>>>(out);
}